// round 8
// baseline (speedup 1.0000x reference)
#include <cuda_runtime.h>
#include <cstdint>
#include <math.h>

#define SEQ  2048
#define BT   4
#define XD   16
#define DM   256
#define NHD  8
#define DH   32
#define DFF  512
#define NL   2
#define ROWS (SEQ*BT)

// ---------------- scratch (static device globals; no allocation) -------------
__device__ float g_h   [ROWS*DM];
__device__ float g_qkv [ROWS*3*DM];
__device__ float g_tmp [ROWS*DM];
__device__ float g_tmp2[ROWS*DM];
__device__ float g_ff  [ROWS*DFF];

// ---------------- embed: tokens = xenc(x) (+ yenc(y) for s < M) --------------
__global__ void embed_kernel(const float* __restrict__ x, const float* __restrict__ y,
                             const int* __restrict__ sep,
                             const float* __restrict__ xw, const float* __restrict__ xb,
                             const float* __restrict__ yw, const float* __restrict__ yb,
                             float* __restrict__ h)
{
    int row = blockIdx.x;           // s*BT + b
    int s = row >> 2, b = row & 3;
    int d = threadIdx.x;            // 0..255
    __shared__ float xs[XD];
    if (threadIdx.x < XD) xs[threadIdx.x] = x[(s*BT + b)*XD + threadIdx.x];
    __syncthreads();
    float acc = xb[d];
    #pragma unroll
    for (int j = 0; j < XD; j++) acc += xs[j] * xw[d*XD + j];
    int M_ = *sep;
    if (s < M_) acc += y[s*BT + b] * yw[d] + yb[d];
    h[row*DM + d] = acc;
}

// ---------------- helpers -----------------------------------------------------
__device__ __forceinline__ float gelu_exact(float v) {
    return 0.5f * v * (1.0f + erff(v * 0.70710678118654752f));
}
__device__ __forceinline__ uint32_t f2tf32(float f) {
    uint32_t r;
    asm("cvt.rna.tf32.f32 %0, %1;" : "=r"(r) : "f"(f));
    return r;
}
__device__ __forceinline__ void mma_tf32(float c[4], const uint32_t a[4], const uint32_t b[2]) {
    asm volatile(
        "mma.sync.aligned.m16n8k8.row.col.f32.tf32.tf32.f32 "
        "{%0,%1,%2,%3}, {%4,%5,%6,%7}, {%8,%9}, {%0,%1,%2,%3};\n"
        : "+f"(c[0]), "+f"(c[1]), "+f"(c[2]), "+f"(c[3])
        : "r"(a[0]), "r"(a[1]), "r"(a[2]), "r"(a[3]), "r"(b[0]), "r"(b[1]));
}

// ---------------- TF32 tensor-core GEMM: C = A (Mr x K) * W^T (N x K) + bias --
// block tile 64x128, BK=16, double-buffered smem, 8 warps (2m x 4n) of 32x32.
template<int ACT>   // 0 = none, 1 = exact gelu
__global__ __launch_bounds__(256)
void gemm_tc(const float* __restrict__ A, const float* __restrict__ W,
             const float* __restrict__ bias, float* __restrict__ C,
             int N, int Kdim, const int* __restrict__ sep_skip)
{
    const int m0 = blockIdx.y * 64;
    const int n0 = blockIdx.x * 128;
    if (sep_skip) {                               // head GEMM: skip blocks fully below M
        int M_ = *sep_skip;
        if (((m0 + 63) >> 2) < M_) return;
    }

    __shared__ uint32_t As[2][64][20];            // m-major, stride 20
    __shared__ uint32_t Bs[2][128][20];           // n-major, stride 20

    const int tid  = threadIdx.x;
    const int lane = tid & 31;
    const int warp = tid >> 5;
    const int grp  = lane >> 2;                   // 0..7
    const int qp   = lane & 3;                    // 0..3
    const int mw   = (warp >> 2) * 32;            // warp m offset (0 or 32)
    const int nw   = (warp & 3) * 32;             // warp n offset (0..96)

    // gmem load mapping
    const int lrA = tid >> 2;                     // 0..63
    const int lcA = (tid & 3) * 4;                // 0,4,8,12
    const int lrB = tid >> 1;                     // 0..127
    const int lcB = (tid & 1) * 8;                // 0 or 8

    float acc[2][4][4];
    #pragma unroll
    for (int mt = 0; mt < 2; mt++)
        #pragma unroll
        for (int nt = 0; nt < 4; nt++)
            #pragma unroll
            for (int e = 0; e < 4; e++) acc[mt][nt][e] = 0.f;

    const int nk = Kdim >> 4;

    // initial tile -> buf 0
    {
        float4 a0 = *(const float4*)&A[(size_t)(m0 + lrA) * Kdim + lcA];
        float4 b0 = *(const float4*)&W[(size_t)(n0 + lrB) * Kdim + lcB];
        float4 b1 = *(const float4*)&W[(size_t)(n0 + lrB) * Kdim + lcB + 4];
        *(uint4*)&As[0][lrA][lcA]     = make_uint4(f2tf32(a0.x), f2tf32(a0.y), f2tf32(a0.z), f2tf32(a0.w));
        *(uint4*)&Bs[0][lrB][lcB]     = make_uint4(f2tf32(b0.x), f2tf32(b0.y), f2tf32(b0.z), f2tf32(b0.w));
        *(uint4*)&Bs[0][lrB][lcB + 4] = make_uint4(f2tf32(b1.x), f2tf32(b1.y), f2tf32(b1.z), f2tf32(b1.w));
    }
    __syncthreads();

    for (int kt = 0; kt < nk; kt++) {
        const int cur = kt & 1;
        float4 pa, pb0, pb1;
        const bool has_next = (kt + 1 < nk);
        if (has_next) {
            int k0 = (kt + 1) << 4;
            pa  = *(const float4*)&A[(size_t)(m0 + lrA) * Kdim + k0 + lcA];
            pb0 = *(const float4*)&W[(size_t)(n0 + lrB) * Kdim + k0 + lcB];
            pb1 = *(const float4*)&W[(size_t)(n0 + lrB) * Kdim + k0 + lcB + 4];
        }

        #pragma unroll
        for (int ks = 0; ks < 16; ks += 8) {
            uint32_t af[2][4], bf[4][2];
            #pragma unroll
            for (int mt = 0; mt < 2; mt++) {
                int m = mw + mt * 16 + grp;
                af[mt][0] = As[cur][m][ks + qp];
                af[mt][1] = As[cur][m + 8][ks + qp];
                af[mt][2] = As[cur][m][ks + qp + 4];
                af[mt][3] = As[cur][m + 8][ks + qp + 4];
            }
            #pragma unroll
            for (int nt = 0; nt < 4; nt++) {
                int n = nw + nt * 8 + grp;
                bf[nt][0] = Bs[cur][n][ks + qp];
                bf[nt][1] = Bs[cur][n][ks + qp + 4];
            }
            #pragma unroll
            for (int mt = 0; mt < 2; mt++)
                #pragma unroll
                for (int nt = 0; nt < 4; nt++)
                    mma_tf32(acc[mt][nt], af[mt], bf[nt]);
        }

        if (has_next) {
            const int nxt = cur ^ 1;
            *(uint4*)&As[nxt][lrA][lcA]     = make_uint4(f2tf32(pa.x),  f2tf32(pa.y),  f2tf32(pa.z),  f2tf32(pa.w));
            *(uint4*)&Bs[nxt][lrB][lcB]     = make_uint4(f2tf32(pb0.x), f2tf32(pb0.y), f2tf32(pb0.z), f2tf32(pb0.w));
            *(uint4*)&Bs[nxt][lrB][lcB + 4] = make_uint4(f2tf32(pb1.x), f2tf32(pb1.y), f2tf32(pb1.z), f2tf32(pb1.w));
            __syncthreads();
        }
    }

    // epilogue: bias + optional gelu, 2-float stores
    #pragma unroll
    for (int nt = 0; nt < 4; nt++) {
        int col = n0 + nw + nt * 8 + qp * 2;
        float b0 = bias[col], b1 = bias[col + 1];
        #pragma unroll
        for (int mt = 0; mt < 2; mt++) {
            int row0 = m0 + mw + mt * 16 + grp;
            float v0 = acc[mt][nt][0] + b0;
            float v1 = acc[mt][nt][1] + b1;
            float v2 = acc[mt][nt][2] + b0;
            float v3 = acc[mt][nt][3] + b1;
            if (ACT == 1) { v0 = gelu_exact(v0); v1 = gelu_exact(v1); v2 = gelu_exact(v2); v3 = gelu_exact(v3); }
            *(float2*)&C[(size_t)row0 * N + col]       = make_float2(v0, v1);
            *(float2*)&C[(size_t)(row0 + 8) * N + col] = make_float2(v2, v3);
        }
    }
}

// ---------------- MMA flash attention -----------------------------------------
// keep = (k < M) | (q == k). Reads qkv [ROWS][768] directly, writes merged
// output [ROWS][256]. CTA: 256 queries x one (b,h); 8 warps x 32 queries.
// K/V pre-converted to tf32 at smem store. Diagonal handled in epilogue.
__global__ __launch_bounds__(256)
void attn_mma(const float* __restrict__ qkv, const int* __restrict__ sep,
              float* __restrict__ out)
{
    const int h = blockIdx.y, b = blockIdx.z;
    const int q0 = blockIdx.x * 256;
    const int tid = threadIdx.x;
    const int w = tid >> 5, lane = tid & 31;
    const int grp = lane >> 2, qp = lane & 3;
    const int M_ = *sep;
    const float scale = 0.17677669529663687f;   // 1/sqrt(32)

    __shared__ float Ks [32][36];               // tf32 bits
    __shared__ float Vts[32][36];               // transposed V, tf32 bits
    __shared__ float Ps [8][32][36];            // per-warp P tile; prologue: Q staging

    // ---- stage Q (256 rows x 32) into Ps area, then load fragments to regs ----
    float* Qst = &Ps[0][0][0];                  // 8*32*36 = 9216 floats = 256*36
    {
        const size_t qbase = ((size_t)q0*4 + b)*768 + (size_t)h*32;
        #pragma unroll
        for (int i = 0; i < 8; i++) {
            int idx = i*256 + tid;              // 0..2047
            int r = idx >> 3, c4 = (idx & 7) * 4;
            float4 qv = *(const float4*)&qkv[qbase + (size_t)r*4*768 + c4];
            *(float4*)&Qst[r*36 + c4] = qv;
        }
    }
    __syncthreads();

    uint32_t qf[2][4][4];
    #pragma unroll
    for (int mt = 0; mt < 2; mt++)
        #pragma unroll
        for (int ks = 0; ks < 4; ks++) {
            int r = w*32 + mt*16 + grp;
            qf[mt][ks][0] = f2tf32(Qst[r*36 + ks*8 + qp]);
            qf[mt][ks][1] = f2tf32(Qst[(r+8)*36 + ks*8 + qp]);
            qf[mt][ks][2] = f2tf32(Qst[r*36 + ks*8 + qp + 4]);
            qf[mt][ks][3] = f2tf32(Qst[(r+8)*36 + ks*8 + qp + 4]);
        }
    // warp w only reads Qst rows later overwritten by warp w itself (Ps[w]) —
    // the first __syncthreads in the chunk loop orders staging reads vs K/V stores.

    float acc_o[2][4][4];
    #pragma unroll
    for (int mt = 0; mt < 2; mt++)
        #pragma unroll
        for (int nt = 0; nt < 4; nt++)
            #pragma unroll
            for (int e = 0; e < 4; e++) acc_o[mt][nt][e] = 0.f;
    float m_st[2][2] = {{-1e30f, -1e30f}, {-1e30f, -1e30f}};
    float l_st[2][2] = {{0.f, 0.f}, {0.f, 0.f}};

    const int nch = (M_ + 31) >> 5;
    for (int c = 0; c < nch; c++) {
        const int kbase = c * 32;
        __syncthreads();
        // load K chunk and V chunk (transposed), converting to tf32 bits
        {
            int r = tid >> 3, c4 = (tid & 7) * 4;
            size_t gro = ((size_t)(kbase + r)*4 + b)*768 + (size_t)h*32 + c4;
            float4 kv = *(const float4*)&qkv[gro + 256];
            Ks[r][c4+0] = __uint_as_float(f2tf32(kv.x));
            Ks[r][c4+1] = __uint_as_float(f2tf32(kv.y));
            Ks[r][c4+2] = __uint_as_float(f2tf32(kv.z));
            Ks[r][c4+3] = __uint_as_float(f2tf32(kv.w));
            float4 vv = *(const float4*)&qkv[gro + 512];
            Vts[c4+0][r] = __uint_as_float(f2tf32(vv.x));
            Vts[c4+1][r] = __uint_as_float(f2tf32(vv.y));
            Vts[c4+2][r] = __uint_as_float(f2tf32(vv.z));
            Vts[c4+3][r] = __uint_as_float(f2tf32(vv.w));
        }
        __syncthreads();

        // ---- S = Q @ K^T (32q x 32k per warp) ----
        float acc_s[2][4][4];
        #pragma unroll
        for (int mt = 0; mt < 2; mt++)
            #pragma unroll
            for (int nt = 0; nt < 4; nt++)
                #pragma unroll
                for (int e = 0; e < 4; e++) acc_s[mt][nt][e] = 0.f;
        #pragma unroll
        for (int nt = 0; nt < 4; nt++)
            #pragma unroll
            for (int ks = 0; ks < 4; ks++) {
                uint32_t bf[2];
                bf[0] = __float_as_uint(Ks[nt*8 + grp][ks*8 + qp]);
                bf[1] = __float_as_uint(Ks[nt*8 + grp][ks*8 + qp + 4]);
                mma_tf32(acc_s[0][nt], qf[0][ks], bf);
                mma_tf32(acc_s[1][nt], qf[1][ks], bf);
            }

        // ---- online softmax update (per thread: 4 rows) ----
        #pragma unroll
        for (int mt = 0; mt < 2; mt++)
            #pragma unroll
            for (int hf = 0; hf < 2; hf++) {
                float sv[4][2];
                float mx = -1e30f;
                #pragma unroll
                for (int nt = 0; nt < 4; nt++)
                    #pragma unroll
                    for (int j = 0; j < 2; j++) {
                        float s = acc_s[mt][nt][hf*2 + j] * scale;
                        int key = kbase + nt*8 + 2*qp + j;
                        if (key >= M_) s = -1e30f;
                        sv[nt][j] = s;
                        mx = fmaxf(mx, s);
                    }
                mx = fmaxf(mx, __shfl_xor_sync(0xffffffffu, mx, 1));
                mx = fmaxf(mx, __shfl_xor_sync(0xffffffffu, mx, 2));
                float m_old = m_st[mt][hf];
                float m_new = fmaxf(m_old, mx);
                float alpha = __expf(m_old - m_new);
                float rs = 0.f;
                int prow = mt*16 + grp + hf*8;
                #pragma unroll
                for (int nt = 0; nt < 4; nt++) {
                    float p0 = __expf(sv[nt][0] - m_new);
                    float p1 = __expf(sv[nt][1] - m_new);
                    rs += p0 + p1;
                    float2 pp = make_float2(__uint_as_float(f2tf32(p0)),
                                            __uint_as_float(f2tf32(p1)));
                    *(float2*)&Ps[w][prow][nt*8 + 2*qp] = pp;
                }
                rs += __shfl_xor_sync(0xffffffffu, rs, 1);
                rs += __shfl_xor_sync(0xffffffffu, rs, 2);
                l_st[mt][hf] = l_st[mt][hf] * alpha + rs;
                m_st[mt][hf] = m_new;
                #pragma unroll
                for (int ntd = 0; ntd < 4; ntd++) {
                    acc_o[mt][ntd][hf*2 + 0] *= alpha;
                    acc_o[mt][ntd][hf*2 + 1] *= alpha;
                }
            }
        __syncwarp();

        // ---- O += P @ V ----
        #pragma unroll
        for (int ks = 0; ks < 4; ks++) {
            uint32_t af[2][4];
            #pragma unroll
            for (int mt = 0; mt < 2; mt++) {
                int r = mt*16 + grp;
                af[mt][0] = __float_as_uint(Ps[w][r][ks*8 + qp]);
                af[mt][1] = __float_as_uint(Ps[w][r + 8][ks*8 + qp]);
                af[mt][2] = __float_as_uint(Ps[w][r][ks*8 + qp + 4]);
                af[mt][3] = __float_as_uint(Ps[w][r + 8][ks*8 + qp + 4]);
            }
            #pragma unroll
            for (int ntd = 0; ntd < 4; ntd++) {
                uint32_t bf[2];
                bf[0] = __float_as_uint(Vts[ntd*8 + grp][ks*8 + qp]);
                bf[1] = __float_as_uint(Vts[ntd*8 + grp][ks*8 + qp + 4]);
                mma_tf32(acc_o[0][ntd], af[0], bf);
                mma_tf32(acc_o[1][ntd], af[1], bf);
            }
        }
    }

    // ---- diagonal key for q >= M ----
    #pragma unroll
    for (int mt = 0; mt < 2; mt++)
        #pragma unroll
        for (int hf = 0; hf < 2; hf++) {
            int q_g = q0 + w*32 + mt*16 + grp + hf*8;
            bool active = (q_g >= M_);
            float part = 0.f;
            size_t rbase = ((size_t)q_g*4 + b)*768 + (size_t)h*32;
            if (active) {
                #pragma unroll
                for (int ks = 0; ks < 4; ks++) {
                    float k0 = qkv[rbase + 256 + ks*8 + qp];
                    float k1 = qkv[rbase + 256 + ks*8 + qp + 4];
                    float qa = __uint_as_float(qf[mt][ks][hf ? 1 : 0]);
                    float qb = __uint_as_float(qf[mt][ks][hf ? 3 : 2]);
                    part += qa*k0 + qb*k1;
                }
            }
            part += __shfl_xor_sync(0xffffffffu, part, 1);
            part += __shfl_xor_sync(0xffffffffu, part, 2);
            if (active) {
                float s_d = part * scale;
                float m_old = m_st[mt][hf];
                float m_new = fmaxf(m_old, s_d);
                float alpha = __expf(m_old - m_new);
                float pd = __expf(s_d - m_new);
                l_st[mt][hf] = l_st[mt][hf] * alpha + pd;
                m_st[mt][hf] = m_new;
                #pragma unroll
                for (int ntd = 0; ntd < 4; ntd++) {
                    float v0 = qkv[rbase + 512 + ntd*8 + 2*qp];
                    float v1 = qkv[rbase + 512 + ntd*8 + 2*qp + 1];
                    acc_o[mt][ntd][hf*2 + 0] = acc_o[mt][ntd][hf*2 + 0]*alpha + pd*v0;
                    acc_o[mt][ntd][hf*2 + 1] = acc_o[mt][ntd][hf*2 + 1]*alpha + pd*v1;
                }
            }
        }

    // ---- finalize: O /= l, store merged [row][h*32+d] ----
    #pragma unroll
    for (int mt = 0; mt < 2; mt++)
        #pragma unroll
        for (int hf = 0; hf < 2; hf++) {
            int q_g = q0 + w*32 + mt*16 + grp + hf*8;
            size_t orow = ((size_t)q_g*4 + b)*256 + (size_t)h*32;
            float inv = 1.f / l_st[mt][hf];
            #pragma unroll
            for (int ntd = 0; ntd < 4; ntd++) {
                float2 o2 = make_float2(acc_o[mt][ntd][hf*2 + 0] * inv,
                                        acc_o[mt][ntd][hf*2 + 1] * inv);
                *(float2*)&out[orow + ntd*8 + 2*qp] = o2;
            }
        }
}

// ---------------- residual add + layer norm ----------------------------------
__global__ void add_ln_kernel(const float* __restrict__ resid,
                              const float* __restrict__ delta,
                              const float* __restrict__ g, const float* __restrict__ bb,
                              float* __restrict__ out)
{
    int row = blockIdx.x;
    int d = threadIdx.x;
    __shared__ float red[DM];
    __shared__ float mu_s, rstd_s;
    float v = resid[(size_t)row*DM + d] + delta[(size_t)row*DM + d];
    red[d] = v;
    __syncthreads();
    for (int off = 128; off > 0; off >>= 1) {
        if (d < off) red[d] += red[d + off];
        __syncthreads();
    }
    if (d == 0) mu_s = red[0] * (1.0f / DM);
    __syncthreads();
    float mu = mu_s;
    float c = v - mu;
    red[d] = c * c;
    __syncthreads();
    for (int off = 128; off > 0; off >>= 1) {
        if (d < off) red[d] += red[d + off];
        __syncthreads();
    }
    if (d == 0) rstd_s = rsqrtf(red[0] * (1.0f / DM) + 1e-5f);
    __syncthreads();
    out[(size_t)row*DM + d] = c * rstd_s * g[d] + bb[d];
}

// ---------------- final head: out[(s-M)*B+b] = hid . w2 + b2 -----------------
__global__ void head2_kernel(const float* __restrict__ hid, const float* __restrict__ w2,
                             const float* __restrict__ b2, const int* __restrict__ sep,
                             float* __restrict__ out)
{
    int row = blockIdx.x;
    int M_ = *sep;
    int s = row >> 2, b = row & 3;
    if (s < M_) return;
    float sum = 0.f;
    for (int t = threadIdx.x; t < DFF; t += 128)
        sum += hid[(size_t)row*DFF + t] * w2[t];
    for (int off = 16; off > 0; off >>= 1)
        sum += __shfl_down_sync(0xffffffffu, sum, off);
    __shared__ float ws[4];
    if ((threadIdx.x & 31) == 0) ws[threadIdx.x >> 5] = sum;
    __syncthreads();
    if (threadIdx.x == 0)
        out[(s - M_)*BT + b] = ws[0] + ws[1] + ws[2] + ws[3] + b2[0];
}

// =============================================================================
extern "C" void kernel_launch(void* const* d_in, const int* in_sizes, int n_in,
                              void* d_out, int out_size)
{
    (void)in_sizes; (void)n_in; (void)out_size;
    const float* x        = (const float*)d_in[0];
    const float* y        = (const float*)d_in[1];
    const int*   sep      = (const int*  )d_in[2];
    const float* xenc_w   = (const float*)d_in[3];
    const float* xenc_b   = (const float*)d_in[4];
    const float* yenc_w   = (const float*)d_in[5];
    const float* yenc_b   = (const float*)d_in[6];
    const float* in_proj_w= (const float*)d_in[7];
    const float* in_proj_b= (const float*)d_in[8];
    const float* out_proj_w=(const float*)d_in[9];
    const float* out_proj_b=(const float*)d_in[10];
    const float* ln1_g    = (const float*)d_in[11];
    const float* ln1_b    = (const float*)d_in[12];
    const float* lin1_w   = (const float*)d_in[13];
    const float* lin1_b   = (const float*)d_in[14];
    const float* lin2_w   = (const float*)d_in[15];
    const float* lin2_b   = (const float*)d_in[16];
    const float* ln2_g    = (const float*)d_in[17];
    const float* ln2_b    = (const float*)d_in[18];
    const float* head_w1  = (const float*)d_in[19];
    const float* head_b1  = (const float*)d_in[20];
    const float* head_w2  = (const float*)d_in[21];
    const float* head_b2  = (const float*)d_in[22];
    float* out = (float*)d_out;

    float *h, *qkv, *tmp, *tmp2, *ff;
    cudaGetSymbolAddress((void**)&h,    g_h);
    cudaGetSymbolAddress((void**)&qkv,  g_qkv);
    cudaGetSymbolAddress((void**)&tmp,  g_tmp);
    cudaGetSymbolAddress((void**)&tmp2, g_tmp2);
    cudaGetSymbolAddress((void**)&ff,   g_ff);

    embed_kernel<<<ROWS, DM>>>(x, y, sep, xenc_w, xenc_b, yenc_w, yenc_b, h);

    for (int l = 0; l < NL; l++) {
        gemm_tc<0><<<dim3(3*DM/128, ROWS/64), 256>>>(
            h, in_proj_w + (size_t)l*3*DM*DM, in_proj_b + (size_t)l*3*DM, qkv, 3*DM, DM, nullptr);
        attn_mma<<<dim3(SEQ/256, NHD, BT), 256>>>(qkv, sep, tmp);
        gemm_tc<0><<<dim3(DM/128, ROWS/64), 256>>>(
            tmp, out_proj_w + (size_t)l*DM*DM, out_proj_b + (size_t)l*DM, tmp2, DM, DM, nullptr);
        add_ln_kernel<<<ROWS, DM>>>(h, tmp2, ln1_g + (size_t)l*DM, ln1_b + (size_t)l*DM, h);
        gemm_tc<1><<<dim3(DFF/128, ROWS/64), 256>>>(
            h, lin1_w + (size_t)l*DFF*DM, lin1_b + (size_t)l*DFF, ff, DFF, DM, nullptr);
        gemm_tc<0><<<dim3(DM/128, ROWS/64), 256>>>(
            ff, lin2_w + (size_t)l*DM*DFF, lin2_b + (size_t)l*DM, tmp2, DM, DFF, nullptr);
        add_ln_kernel<<<ROWS, DM>>>(h, tmp2, ln2_g + (size_t)l*DM, ln2_b + (size_t)l*DM, h);
    }

    gemm_tc<1><<<dim3(DFF/128, ROWS/64), 256>>>(h, head_w1, head_b1, ff, DFF, DM, sep);
    head2_kernel<<<ROWS, 128>>>(ff, head_w2, head_b2, sep, out);
}

// round 9
// speedup vs baseline: 1.1622x; 1.1622x over previous
#include <cuda_runtime.h>
#include <cstdint>
#include <math.h>

#define SEQ  2048
#define BT   4
#define XD   16
#define DM   256
#define NHD  8
#define DH   32
#define DFF  512
#define NL   2
#define ROWS (SEQ*BT)

#define STAGES 3
// smem floats for gemm: STAGES*(64*20 + 256*20) = 19200 floats = 76.8 KB
#define GEMM_SMEM_FLOATS (STAGES * (64 * 20 + 256 * 20))

// ---------------- scratch (static device globals; no allocation) -------------
__device__ float g_h   [ROWS*DM];
__device__ float g_qkv [ROWS*3*DM];
__device__ float g_tmp [ROWS*DM];
__device__ float g_ff  [ROWS*DFF];

// ---------------- embed: tokens = xenc(x) (+ yenc(y) for s < M) --------------
__global__ void embed_kernel(const float* __restrict__ x, const float* __restrict__ y,
                             const int* __restrict__ sep,
                             const float* __restrict__ xw, const float* __restrict__ xb,
                             const float* __restrict__ yw, const float* __restrict__ yb,
                             float* __restrict__ h)
{
    int row = blockIdx.x;           // s*BT + b
    int s = row >> 2, b = row & 3;
    int d = threadIdx.x;            // 0..255
    __shared__ float xs[XD];
    if (threadIdx.x < XD) xs[threadIdx.x] = x[(s*BT + b)*XD + threadIdx.x];
    __syncthreads();
    float acc = xb[d];
    #pragma unroll
    for (int j = 0; j < XD; j++) acc += xs[j] * xw[d*XD + j];
    int M_ = *sep;
    if (s < M_) acc += y[s*BT + b] * yw[d] + yb[d];
    h[row*DM + d] = acc;
}

// ---------------- helpers -----------------------------------------------------
__device__ __forceinline__ float gelu_exact(float v) {
    return 0.5f * v * (1.0f + erff(v * 0.70710678118654752f));
}
__device__ __forceinline__ uint32_t f2tf32(float f) {
    uint32_t r;
    asm("cvt.rna.tf32.f32 %0, %1;" : "=r"(r) : "f"(f));
    return r;
}
__device__ __forceinline__ void mma_tf32(float c[4], const uint32_t a[4], const uint32_t b[2]) {
    asm volatile(
        "mma.sync.aligned.m16n8k8.row.col.f32.tf32.tf32.f32 "
        "{%0,%1,%2,%3}, {%4,%5,%6,%7}, {%8,%9}, {%0,%1,%2,%3};\n"
        : "+f"(c[0]), "+f"(c[1]), "+f"(c[2]), "+f"(c[3])
        : "r"(a[0]), "r"(a[1]), "r"(a[2]), "r"(a[3]), "r"(b[0]), "r"(b[1]));
}
__device__ __forceinline__ void cp16(uint32_t dst, const void* src) {
    asm volatile("cp.async.cg.shared.global [%0], [%1], 16;" :: "r"(dst), "l"(src));
}
__device__ __forceinline__ void cp_commit() {
    asm volatile("cp.async.commit_group;");
}
__device__ __forceinline__ void cp_wait1() {
    asm volatile("cp.async.wait_group 1;");
}

// ---------------- TF32 tensor-core GEMM: C = A (Mr x K) * W^T (N x K) + bias --
// block tile 64x256, BK=16, 3-stage cp.async pipeline, 8 warps (2m x 4n) 32x64.
// FUSE=1: C = layernorm(resid + A*W^T + bias) with gains lng / offsets lnb.
template<int ACT, int FUSE>
__global__ __launch_bounds__(256, 2)
void gemm_tc(const float* __restrict__ A, const float* __restrict__ W,
             const float* __restrict__ bias, float* C,
             const float* resid, const float* __restrict__ lng,
             const float* __restrict__ lnb,
             int N, int Kdim, const int* __restrict__ sep_skip)
{
    const int m0 = blockIdx.y * 64;
    const int n0 = blockIdx.x * 256;
    if (sep_skip) {                               // head GEMM: skip blocks fully below M
        int M_ = *sep_skip;
        if (((m0 + 63) >> 2) < M_) return;
    }

    extern __shared__ float sm[];
    float* Asb = sm;                              // [STAGES][64][20]
    float* Bsb = sm + STAGES * 64 * 20;           // [STAGES][256][20]

    const int tid  = threadIdx.x;
    const int lane = tid & 31;
    const int warp = tid >> 5;
    const int grp  = lane >> 2;                   // 0..7
    const int qp   = lane & 3;                    // 0..3
    const int mw   = (warp >> 2) * 32;            // warp m offset (0 or 32)
    const int nw   = (warp & 3) * 64;             // warp n offset (0..192)

    const int rT = tid >> 2;                      // 0..63
    const int cT = (tid & 3) * 4;                 // 0,4,8,12

    const uint32_t asb_u = (uint32_t)__cvta_generic_to_shared(Asb);
    const uint32_t bsb_u = (uint32_t)__cvta_generic_to_shared(Bsb);

    const int nk = Kdim >> 4;

    // stage copy: tile kt into stage s
    auto issue_tile = [&](int s, int kt) {
        int k0 = kt << 4;
        cp16(asb_u + (((s*64 + rT)*20 + cT) << 2),
             &A[(size_t)(m0 + rT) * Kdim + k0 + cT]);
        #pragma unroll
        for (int i = 0; i < 4; i++) {
            int row = rT + i * 64;
            cp16(bsb_u + (((s*256 + row)*20 + cT) << 2),
                 &W[(size_t)(n0 + row) * Kdim + k0 + cT]);
        }
        cp_commit();
    };

    float acc[2][8][4];
    #pragma unroll
    for (int mt = 0; mt < 2; mt++)
        #pragma unroll
        for (int nt = 0; nt < 8; nt++)
            #pragma unroll
            for (int e = 0; e < 4; e++) acc[mt][nt][e] = 0.f;

    issue_tile(0, 0);
    issue_tile(1, 1);

    for (int kt = 0; kt < nk; kt++) {
        const int st = kt % STAGES;
        cp_wait1();                                // tile kt resident
        __syncthreads();
        if (kt + 2 < nk) issue_tile((kt + 2) % STAGES, kt + 2);
        else             cp_commit();              // empty group keeps wait bookkeeping

        const float* As = Asb + st * 64 * 20;
        const float* Bs = Bsb + st * 256 * 20;
        #pragma unroll
        for (int ks = 0; ks < 16; ks += 8) {
            uint32_t af[2][4], bf[8][2];
            #pragma unroll
            for (int mt = 0; mt < 2; mt++) {
                int m = mw + mt * 16 + grp;
                af[mt][0] = f2tf32(As[m*20 + ks + qp]);
                af[mt][1] = f2tf32(As[(m+8)*20 + ks + qp]);
                af[mt][2] = f2tf32(As[m*20 + ks + qp + 4]);
                af[mt][3] = f2tf32(As[(m+8)*20 + ks + qp + 4]);
            }
            #pragma unroll
            for (int nt = 0; nt < 8; nt++) {
                int n = nw + nt * 8 + grp;
                bf[nt][0] = f2tf32(Bs[n*20 + ks + qp]);
                bf[nt][1] = f2tf32(Bs[n*20 + ks + qp + 4]);
            }
            #pragma unroll
            for (int mt = 0; mt < 2; mt++)
                #pragma unroll
                for (int nt = 0; nt < 8; nt++)
                    mma_tf32(acc[mt][nt], af[mt], bf[nt]);
        }
    }

    if (!FUSE) {
        // plain epilogue: bias + optional gelu
        #pragma unroll
        for (int nt = 0; nt < 8; nt++) {
            int col = n0 + nw + nt * 8 + qp * 2;
            float b0 = bias[col], b1 = bias[col + 1];
            #pragma unroll
            for (int mt = 0; mt < 2; mt++) {
                int row0 = m0 + mw + mt * 16 + grp;
                float v0 = acc[mt][nt][0] + b0;
                float v1 = acc[mt][nt][1] + b1;
                float v2 = acc[mt][nt][2] + b0;
                float v3 = acc[mt][nt][3] + b1;
                if (ACT == 1) { v0 = gelu_exact(v0); v1 = gelu_exact(v1); v2 = gelu_exact(v2); v3 = gelu_exact(v3); }
                *(float2*)&C[(size_t)row0 * N + col]       = make_float2(v0, v1);
                *(float2*)&C[(size_t)(row0 + 8) * N + col] = make_float2(v2, v3);
            }
        }
    } else {
        // fused residual + layernorm epilogue (N == 256, n0 == 0)
        float* Ct = sm;                           // [64][260] carve, 16640 <= 19200 floats
        __syncthreads();                          // all stage reads done; reuse smem
        #pragma unroll
        for (int nt = 0; nt < 8; nt++) {
            int col = nw + nt * 8 + qp * 2;
            float b0 = bias[col], b1 = bias[col + 1];
            #pragma unroll
            for (int mt = 0; mt < 2; mt++) {
                int r0 = mw + mt * 16 + grp;
                *(float2*)&Ct[r0*260 + col]     = make_float2(acc[mt][nt][0] + b0, acc[mt][nt][1] + b1);
                *(float2*)&Ct[(r0+8)*260 + col] = make_float2(acc[mt][nt][2] + b0, acc[mt][nt][3] + b1);
            }
        }
        __syncthreads();

        const int row = tid >> 2;                 // 0..63
        const int qq  = tid & 3;                  // quarter of the 256 cols
        const size_t grow = (size_t)(m0 + row);
        float sum = 0.f, ss = 0.f;
        #pragma unroll
        for (int i = 0; i < 16; i++) {
            int c = qq * 64 + i * 4;
            float4 cv = *(float4*)&Ct[row*260 + c];
            float4 rv = *(const float4*)&resid[grow*256 + c];
            cv.x += rv.x; cv.y += rv.y; cv.z += rv.z; cv.w += rv.w;
            *(float4*)&Ct[row*260 + c] = cv;
            sum += cv.x + cv.y + cv.z + cv.w;
            ss  += cv.x*cv.x + cv.y*cv.y + cv.z*cv.z + cv.w*cv.w;
        }
        sum += __shfl_xor_sync(0xffffffffu, sum, 1);
        sum += __shfl_xor_sync(0xffffffffu, sum, 2);
        ss  += __shfl_xor_sync(0xffffffffu, ss, 1);
        ss  += __shfl_xor_sync(0xffffffffu, ss, 2);
        float mu = sum * (1.0f / 256.0f);
        float rstd = rsqrtf(ss * (1.0f / 256.0f) - mu * mu + 1e-5f);
        #pragma unroll
        for (int i = 0; i < 16; i++) {
            int c = qq * 64 + i * 4;
            float4 cv = *(float4*)&Ct[row*260 + c];
            float4 g4 = *(const float4*)&lng[c];
            float4 b4 = *(const float4*)&lnb[c];
            float4 o;
            o.x = (cv.x - mu) * rstd * g4.x + b4.x;
            o.y = (cv.y - mu) * rstd * g4.y + b4.y;
            o.z = (cv.z - mu) * rstd * g4.z + b4.z;
            o.w = (cv.w - mu) * rstd * g4.w + b4.w;
            *(float4*)&C[grow*256 + c] = o;
        }
    }
}

// ---------------- MMA flash attention -----------------------------------------
// keep = (k < M) | (q == k). Reads qkv [ROWS][768] directly, writes merged
// output [ROWS][256]. CTA: 256 queries x one (b,h); 8 warps x 32 queries.
__global__ __launch_bounds__(256)
void attn_mma(const float* __restrict__ qkv, const int* __restrict__ sep,
              float* __restrict__ out)
{
    const int h = blockIdx.y, b = blockIdx.z;
    const int q0 = blockIdx.x * 256;
    const int tid = threadIdx.x;
    const int w = tid >> 5, lane = tid & 31;
    const int grp = lane >> 2, qp = lane & 3;
    const int M_ = *sep;
    const float scale = 0.17677669529663687f;   // 1/sqrt(32)

    __shared__ float Ks [32][36];               // tf32 bits
    __shared__ float Vts[32][36];               // transposed V, tf32 bits
    __shared__ float Ps [8][32][36];            // per-warp P tile; prologue: Q staging

    float* Qst = &Ps[0][0][0];                  // 8*32*36 = 9216 floats = 256*36
    {
        const size_t qbase = ((size_t)q0*4 + b)*768 + (size_t)h*32;
        #pragma unroll
        for (int i = 0; i < 8; i++) {
            int idx = i*256 + tid;
            int r = idx >> 3, c4 = (idx & 7) * 4;
            float4 qv = *(const float4*)&qkv[qbase + (size_t)r*4*768 + c4];
            *(float4*)&Qst[r*36 + c4] = qv;
        }
    }
    __syncthreads();

    uint32_t qf[2][4][4];
    #pragma unroll
    for (int mt = 0; mt < 2; mt++)
        #pragma unroll
        for (int ks = 0; ks < 4; ks++) {
            int r = w*32 + mt*16 + grp;
            qf[mt][ks][0] = f2tf32(Qst[r*36 + ks*8 + qp]);
            qf[mt][ks][1] = f2tf32(Qst[(r+8)*36 + ks*8 + qp]);
            qf[mt][ks][2] = f2tf32(Qst[r*36 + ks*8 + qp + 4]);
            qf[mt][ks][3] = f2tf32(Qst[(r+8)*36 + ks*8 + qp + 4]);
        }

    float acc_o[2][4][4];
    #pragma unroll
    for (int mt = 0; mt < 2; mt++)
        #pragma unroll
        for (int nt = 0; nt < 4; nt++)
            #pragma unroll
            for (int e = 0; e < 4; e++) acc_o[mt][nt][e] = 0.f;
    float m_st[2][2] = {{-1e30f, -1e30f}, {-1e30f, -1e30f}};
    float l_st[2][2] = {{0.f, 0.f}, {0.f, 0.f}};

    const int nch = (M_ + 31) >> 5;
    for (int c = 0; c < nch; c++) {
        const int kbase = c * 32;
        __syncthreads();
        {
            int r = tid >> 3, c4 = (tid & 7) * 4;
            size_t gro = ((size_t)(kbase + r)*4 + b)*768 + (size_t)h*32 + c4;
            float4 kv = *(const float4*)&qkv[gro + 256];
            Ks[r][c4+0] = __uint_as_float(f2tf32(kv.x));
            Ks[r][c4+1] = __uint_as_float(f2tf32(kv.y));
            Ks[r][c4+2] = __uint_as_float(f2tf32(kv.z));
            Ks[r][c4+3] = __uint_as_float(f2tf32(kv.w));
            float4 vv = *(const float4*)&qkv[gro + 512];
            Vts[c4+0][r] = __uint_as_float(f2tf32(vv.x));
            Vts[c4+1][r] = __uint_as_float(f2tf32(vv.y));
            Vts[c4+2][r] = __uint_as_float(f2tf32(vv.z));
            Vts[c4+3][r] = __uint_as_float(f2tf32(vv.w));
        }
        __syncthreads();

        float acc_s[2][4][4];
        #pragma unroll
        for (int mt = 0; mt < 2; mt++)
            #pragma unroll
            for (int nt = 0; nt < 4; nt++)
                #pragma unroll
                for (int e = 0; e < 4; e++) acc_s[mt][nt][e] = 0.f;
        #pragma unroll
        for (int nt = 0; nt < 4; nt++)
            #pragma unroll
            for (int ks = 0; ks < 4; ks++) {
                uint32_t bf[2];
                bf[0] = __float_as_uint(Ks[nt*8 + grp][ks*8 + qp]);
                bf[1] = __float_as_uint(Ks[nt*8 + grp][ks*8 + qp + 4]);
                mma_tf32(acc_s[0][nt], qf[0][ks], bf);
                mma_tf32(acc_s[1][nt], qf[1][ks], bf);
            }

        #pragma unroll
        for (int mt = 0; mt < 2; mt++)
            #pragma unroll
            for (int hf = 0; hf < 2; hf++) {
                float sv[4][2];
                float mx = -1e30f;
                #pragma unroll
                for (int nt = 0; nt < 4; nt++)
                    #pragma unroll
                    for (int j = 0; j < 2; j++) {
                        float s = acc_s[mt][nt][hf*2 + j] * scale;
                        int key = kbase + nt*8 + 2*qp + j;
                        if (key >= M_) s = -1e30f;
                        sv[nt][j] = s;
                        mx = fmaxf(mx, s);
                    }
                mx = fmaxf(mx, __shfl_xor_sync(0xffffffffu, mx, 1));
                mx = fmaxf(mx, __shfl_xor_sync(0xffffffffu, mx, 2));
                float m_old = m_st[mt][hf];
                float m_new = fmaxf(m_old, mx);
                float alpha = __expf(m_old - m_new);
                float rs = 0.f;
                int prow = mt*16 + grp + hf*8;
                #pragma unroll
                for (int nt = 0; nt < 4; nt++) {
                    float p0 = __expf(sv[nt][0] - m_new);
                    float p1 = __expf(sv[nt][1] - m_new);
                    rs += p0 + p1;
                    float2 pp = make_float2(__uint_as_float(f2tf32(p0)),
                                            __uint_as_float(f2tf32(p1)));
                    *(float2*)&Ps[w][prow][nt*8 + 2*qp] = pp;
                }
                rs += __shfl_xor_sync(0xffffffffu, rs, 1);
                rs += __shfl_xor_sync(0xffffffffu, rs, 2);
                l_st[mt][hf] = l_st[mt][hf] * alpha + rs;
                m_st[mt][hf] = m_new;
                #pragma unroll
                for (int ntd = 0; ntd < 4; ntd++) {
                    acc_o[mt][ntd][hf*2 + 0] *= alpha;
                    acc_o[mt][ntd][hf*2 + 1] *= alpha;
                }
            }
        __syncwarp();

        #pragma unroll
        for (int ks = 0; ks < 4; ks++) {
            uint32_t af[2][4];
            #pragma unroll
            for (int mt = 0; mt < 2; mt++) {
                int r = mt*16 + grp;
                af[mt][0] = __float_as_uint(Ps[w][r][ks*8 + qp]);
                af[mt][1] = __float_as_uint(Ps[w][r + 8][ks*8 + qp]);
                af[mt][2] = __float_as_uint(Ps[w][r][ks*8 + qp + 4]);
                af[mt][3] = __float_as_uint(Ps[w][r + 8][ks*8 + qp + 4]);
            }
            #pragma unroll
            for (int ntd = 0; ntd < 4; ntd++) {
                uint32_t bf[2];
                bf[0] = __float_as_uint(Vts[ntd*8 + grp][ks*8 + qp]);
                bf[1] = __float_as_uint(Vts[ntd*8 + grp][ks*8 + qp + 4]);
                mma_tf32(acc_o[0][ntd], af[0], bf);
                mma_tf32(acc_o[1][ntd], af[1], bf);
            }
        }
    }

    // ---- diagonal key for q >= M ----
    #pragma unroll
    for (int mt = 0; mt < 2; mt++)
        #pragma unroll
        for (int hf = 0; hf < 2; hf++) {
            int q_g = q0 + w*32 + mt*16 + grp + hf*8;
            bool active = (q_g >= M_);
            float part = 0.f;
            size_t rbase = ((size_t)q_g*4 + b)*768 + (size_t)h*32;
            if (active) {
                #pragma unroll
                for (int ks = 0; ks < 4; ks++) {
                    float k0 = qkv[rbase + 256 + ks*8 + qp];
                    float k1 = qkv[rbase + 256 + ks*8 + qp + 4];
                    float qa = __uint_as_float(qf[mt][ks][hf ? 1 : 0]);
                    float qb = __uint_as_float(qf[mt][ks][hf ? 3 : 2]);
                    part += qa*k0 + qb*k1;
                }
            }
            part += __shfl_xor_sync(0xffffffffu, part, 1);
            part += __shfl_xor_sync(0xffffffffu, part, 2);
            if (active) {
                float s_d = part * scale;
                float m_old = m_st[mt][hf];
                float m_new = fmaxf(m_old, s_d);
                float alpha = __expf(m_old - m_new);
                float pd = __expf(s_d - m_new);
                l_st[mt][hf] = l_st[mt][hf] * alpha + pd;
                m_st[mt][hf] = m_new;
                #pragma unroll
                for (int ntd = 0; ntd < 4; ntd++) {
                    float v0 = qkv[rbase + 512 + ntd*8 + 2*qp];
                    float v1 = qkv[rbase + 512 + ntd*8 + 2*qp + 1];
                    acc_o[mt][ntd][hf*2 + 0] = acc_o[mt][ntd][hf*2 + 0]*alpha + pd*v0;
                    acc_o[mt][ntd][hf*2 + 1] = acc_o[mt][ntd][hf*2 + 1]*alpha + pd*v1;
                }
            }
        }

    // ---- finalize ----
    #pragma unroll
    for (int mt = 0; mt < 2; mt++)
        #pragma unroll
        for (int hf = 0; hf < 2; hf++) {
            int q_g = q0 + w*32 + mt*16 + grp + hf*8;
            size_t orow = ((size_t)q_g*4 + b)*256 + (size_t)h*32;
            float inv = 1.f / l_st[mt][hf];
            #pragma unroll
            for (int ntd = 0; ntd < 4; ntd++) {
                float2 o2 = make_float2(acc_o[mt][ntd][hf*2 + 0] * inv,
                                        acc_o[mt][ntd][hf*2 + 1] * inv);
                *(float2*)&out[orow + ntd*8 + 2*qp] = o2;
            }
        }
}

// ---------------- final head: out[(s-M)*B+b] = hid . w2 + b2 -----------------
__global__ void head2_kernel(const float* __restrict__ hid, const float* __restrict__ w2,
                             const float* __restrict__ b2, const int* __restrict__ sep,
                             float* __restrict__ out)
{
    int row = blockIdx.x;
    int M_ = *sep;
    int s = row >> 2, b = row & 3;
    if (s < M_) return;
    float sum = 0.f;
    for (int t = threadIdx.x; t < DFF; t += 128)
        sum += hid[(size_t)row*DFF + t] * w2[t];
    for (int off = 16; off > 0; off >>= 1)
        sum += __shfl_down_sync(0xffffffffu, sum, off);
    __shared__ float ws[4];
    if ((threadIdx.x & 31) == 0) ws[threadIdx.x >> 5] = sum;
    __syncthreads();
    if (threadIdx.x == 0)
        out[(s - M_)*BT + b] = ws[0] + ws[1] + ws[2] + ws[3] + b2[0];
}

// =============================================================================
extern "C" void kernel_launch(void* const* d_in, const int* in_sizes, int n_in,
                              void* d_out, int out_size)
{
    (void)in_sizes; (void)n_in; (void)out_size;
    const float* x        = (const float*)d_in[0];
    const float* y        = (const float*)d_in[1];
    const int*   sep      = (const int*  )d_in[2];
    const float* xenc_w   = (const float*)d_in[3];
    const float* xenc_b   = (const float*)d_in[4];
    const float* yenc_w   = (const float*)d_in[5];
    const float* yenc_b   = (const float*)d_in[6];
    const float* in_proj_w= (const float*)d_in[7];
    const float* in_proj_b= (const float*)d_in[8];
    const float* out_proj_w=(const float*)d_in[9];
    const float* out_proj_b=(const float*)d_in[10];
    const float* ln1_g    = (const float*)d_in[11];
    const float* ln1_b    = (const float*)d_in[12];
    const float* lin1_w   = (const float*)d_in[13];
    const float* lin1_b   = (const float*)d_in[14];
    const float* lin2_w   = (const float*)d_in[15];
    const float* lin2_b   = (const float*)d_in[16];
    const float* ln2_g    = (const float*)d_in[17];
    const float* ln2_b    = (const float*)d_in[18];
    const float* head_w1  = (const float*)d_in[19];
    const float* head_b1  = (const float*)d_in[20];
    const float* head_w2  = (const float*)d_in[21];
    const float* head_b2  = (const float*)d_in[22];
    float* out = (float*)d_out;

    float *h, *qkv, *tmp, *ff;
    cudaGetSymbolAddress((void**)&h,    g_h);
    cudaGetSymbolAddress((void**)&qkv,  g_qkv);
    cudaGetSymbolAddress((void**)&tmp,  g_tmp);
    cudaGetSymbolAddress((void**)&ff,   g_ff);

    const int smem_bytes = GEMM_SMEM_FLOATS * 4;
    cudaFuncSetAttribute(gemm_tc<0,0>, cudaFuncAttributeMaxDynamicSharedMemorySize, smem_bytes);
    cudaFuncSetAttribute(gemm_tc<0,1>, cudaFuncAttributeMaxDynamicSharedMemorySize, smem_bytes);
    cudaFuncSetAttribute(gemm_tc<1,0>, cudaFuncAttributeMaxDynamicSharedMemorySize, smem_bytes);

    embed_kernel<<<ROWS, DM>>>(x, y, sep, xenc_w, xenc_b, yenc_w, yenc_b, h);

    for (int l = 0; l < NL; l++) {
        // QKV projection: (8192 x 256) x (768 x 256)^T
        gemm_tc<0,0><<<dim3(3, ROWS/64), 256, smem_bytes>>>(
            h, in_proj_w + (size_t)l*3*DM*DM, in_proj_b + (size_t)l*3*DM, qkv,
            nullptr, nullptr, nullptr, 3*DM, DM, nullptr);
        attn_mma<<<dim3(SEQ/256, NHD, BT), 256>>>(qkv, sep, tmp);
        // out projection fused with residual+LN -> writes h
        gemm_tc<0,1><<<dim3(1, ROWS/64), 256, smem_bytes>>>(
            tmp, out_proj_w + (size_t)l*DM*DM, out_proj_b + (size_t)l*DM, h,
            h, ln1_g + (size_t)l*DM, ln1_b + (size_t)l*DM, DM, DM, nullptr);
        // FF up with gelu
        gemm_tc<1,0><<<dim3(2, ROWS/64), 256, smem_bytes>>>(
            h, lin1_w + (size_t)l*DFF*DM, lin1_b + (size_t)l*DFF, ff,
            nullptr, nullptr, nullptr, DFF, DM, nullptr);
        // FF down fused with residual+LN -> writes h
        gemm_tc<0,1><<<dim3(1, ROWS/64), 256, smem_bytes>>>(
            ff, lin2_w + (size_t)l*DM*DFF, lin2_b + (size_t)l*DM, h,
            h, ln2_g + (size_t)l*DM, ln2_b + (size_t)l*DM, DM, DFF, nullptr);
    }

    gemm_tc<1,0><<<dim3(2, ROWS/64), 256, smem_bytes>>>(
        h, head_w1, head_b1, ff, nullptr, nullptr, nullptr, DFF, DM, sep);
    head2_kernel<<<ROWS, 128>>>(ff, head_w2, head_b2, sep, out);
}

// round 11
// speedup vs baseline: 1.2268x; 1.0557x over previous
#include <cuda_runtime.h>
#include <cstdint>
#include <math.h>

#define SEQ  2048
#define BT   4
#define XD   16
#define DM   256
#define NHD  8
#define DH   32
#define DFF  512
#define NL   2
#define ROWS (SEQ*BT)

// fused gemm: 3 stages x (64 + 256) rows x 36 floats
#define FUSE_SMEM_FLOATS (3 * (64 + 256) * 36)
// non-fused gemm: 3 stages x (64 + 128) rows x 36 floats
#define NF_SMEM_FLOATS   (3 * (64 + 128) * 36)

// ---------------- scratch (static device globals; no allocation) -------------
__device__ float g_h   [ROWS*DM];
__device__ float g_qkv [ROWS*3*DM];
__device__ float g_tmp [ROWS*DM];
__device__ float g_ff  [ROWS*DFF];

// ---------------- embed: tokens = xenc(x) (+ yenc(y) for s < M) --------------
__global__ void embed_kernel(const float* __restrict__ x, const float* __restrict__ y,
                             const int* __restrict__ sep,
                             const float* __restrict__ xw, const float* __restrict__ xb,
                             const float* __restrict__ yw, const float* __restrict__ yb,
                             float* __restrict__ h)
{
    int row = blockIdx.x;           // s*BT + b
    int s = row >> 2, b = row & 3;
    int d = threadIdx.x;            // 0..255
    __shared__ float xs[XD];
    if (threadIdx.x < XD) xs[threadIdx.x] = x[(s*BT + b)*XD + threadIdx.x];
    __syncthreads();
    float acc = xb[d];
    #pragma unroll
    for (int j = 0; j < XD; j++) acc += xs[j] * xw[d*XD + j];
    int M_ = *sep;
    if (s < M_) acc += y[s*BT + b] * yw[d] + yb[d];
    h[row*DM + d] = acc;
}

// ---------------- helpers -----------------------------------------------------
__device__ __forceinline__ float gelu_exact(float v) {
    return 0.5f * v * (1.0f + erff(v * 0.70710678118654752f));
}
__device__ __forceinline__ uint32_t f2tf32(float f) {
    uint32_t r;
    asm("cvt.rna.tf32.f32 %0, %1;" : "=r"(r) : "f"(f));
    return r;
}
__device__ __forceinline__ void mma_tf32(float c[4], const uint32_t a[4], const uint32_t b[2]) {
    asm volatile(
        "mma.sync.aligned.m16n8k8.row.col.f32.tf32.tf32.f32 "
        "{%0,%1,%2,%3}, {%4,%5,%6,%7}, {%8,%9}, {%0,%1,%2,%3};\n"
        : "+f"(c[0]), "+f"(c[1]), "+f"(c[2]), "+f"(c[3])
        : "r"(a[0]), "r"(a[1]), "r"(a[2]), "r"(a[3]), "r"(b[0]), "r"(b[1]));
}
__device__ __forceinline__ void cp16(uint32_t dst, const void* src) {
    asm volatile("cp.async.cg.shared.global [%0], [%1], 16;" :: "r"(dst), "l"(src));
}
__device__ __forceinline__ void cp_commit() {
    asm volatile("cp.async.commit_group;");
}
__device__ __forceinline__ void cp_wait1() {
    asm volatile("cp.async.wait_group 1;");
}

// ================= fused GEMM + residual + layernorm ==========================
// C(row-major, N=256) = layernorm(resid + A(64-rows) * W^T + bias)
// block 64x256, BK=32, 3-stage cp.async, 8 warps (2m x 4n) of 32x64.
__global__ __launch_bounds__(256)
void gemm_fuse(const float* __restrict__ A, const float* __restrict__ W,
               const float* __restrict__ bias, float* C,
               const float* resid, const float* __restrict__ lng,
               const float* __restrict__ lnb, int Kdim)
{
    const int m0 = blockIdx.y * 64;

    extern __shared__ float sm[];
    float* Asb = sm;                              // [3][64][36]
    float* Bsb = sm + 3 * 64 * 36;                // [3][256][36]

    const int tid  = threadIdx.x;
    const int lane = tid & 31;
    const int warp = tid >> 5;
    const int grp  = lane >> 2;
    const int qp   = lane & 3;
    const int mw   = (warp >> 2) * 32;
    const int nw   = (warp & 3) * 64;

    const uint32_t asb_u = (uint32_t)__cvta_generic_to_shared(Asb);
    const uint32_t bsb_u = (uint32_t)__cvta_generic_to_shared(Bsb);

    const int nk = Kdim >> 5;

    auto issue_tile = [&](int s, int kt) {
        int k0 = kt << 5;
        #pragma unroll
        for (int i = 0; i < 2; i++) {             // A: 64 rows x 8 float4
            int idx = i*256 + tid;
            int r = idx >> 3, c4 = (idx & 7) * 4;
            cp16(asb_u + (((s*64 + r)*36 + c4) << 2),
                 &A[(size_t)(m0 + r) * Kdim + k0 + c4]);
        }
        #pragma unroll
        for (int i = 0; i < 8; i++) {             // B: 256 rows x 8 float4
            int idx = i*256 + tid;
            int r = idx >> 3, c4 = (idx & 7) * 4;
            cp16(bsb_u + (((s*256 + r)*36 + c4) << 2),
                 &W[(size_t)r * Kdim + k0 + c4]);
        }
        cp_commit();
    };

    float acc[2][8][4];
    #pragma unroll
    for (int mt = 0; mt < 2; mt++)
        #pragma unroll
        for (int nt = 0; nt < 8; nt++)
            #pragma unroll
            for (int e = 0; e < 4; e++) acc[mt][nt][e] = 0.f;

    issue_tile(0, 0);
    issue_tile(1, 1);

    for (int kt = 0; kt < nk; kt++) {
        const int st = kt % 3;
        cp_wait1();
        __syncthreads();
        if (kt + 2 < nk) issue_tile((kt + 2) % 3, kt + 2);
        else             cp_commit();

        const float* As = Asb + st * 64 * 36;
        const float* Bs = Bsb + st * 256 * 36;
        #pragma unroll
        for (int ks = 0; ks < 32; ks += 8) {
            uint32_t af[2][4], bf[8][2];
            #pragma unroll
            for (int mt = 0; mt < 2; mt++) {
                int m = mw + mt * 16 + grp;
                af[mt][0] = f2tf32(As[m*36 + ks + qp]);
                af[mt][1] = f2tf32(As[(m+8)*36 + ks + qp]);
                af[mt][2] = f2tf32(As[m*36 + ks + qp + 4]);
                af[mt][3] = f2tf32(As[(m+8)*36 + ks + qp + 4]);
            }
            #pragma unroll
            for (int nt = 0; nt < 8; nt++) {
                int n = nw + nt * 8 + grp;
                bf[nt][0] = f2tf32(Bs[n*36 + ks + qp]);
                bf[nt][1] = f2tf32(Bs[n*36 + ks + qp + 4]);
            }
            #pragma unroll
            for (int mt = 0; mt < 2; mt++)
                #pragma unroll
                for (int nt = 0; nt < 8; nt++)
                    mma_tf32(acc[mt][nt], af[mt], bf[nt]);
        }
    }

    // fused residual + layernorm epilogue
    float* Ct = sm;                               // [64][260] carve
    __syncthreads();
    #pragma unroll
    for (int nt = 0; nt < 8; nt++) {
        int col = nw + nt * 8 + qp * 2;
        float b0 = bias[col], b1 = bias[col + 1];
        #pragma unroll
        for (int mt = 0; mt < 2; mt++) {
            int r0 = mw + mt * 16 + grp;
            *(float2*)&Ct[r0*260 + col]     = make_float2(acc[mt][nt][0] + b0, acc[mt][nt][1] + b1);
            *(float2*)&Ct[(r0+8)*260 + col] = make_float2(acc[mt][nt][2] + b0, acc[mt][nt][3] + b1);
        }
    }
    __syncthreads();

    const int row = tid >> 2;
    const int qq  = tid & 3;
    const size_t grow = (size_t)(m0 + row);
    float sum = 0.f, ss = 0.f;
    #pragma unroll
    for (int i = 0; i < 16; i++) {
        int c = qq * 64 + i * 4;
        float4 cv = *(float4*)&Ct[row*260 + c];
        float4 rv = *(const float4*)&resid[grow*256 + c];
        cv.x += rv.x; cv.y += rv.y; cv.z += rv.z; cv.w += rv.w;
        *(float4*)&Ct[row*260 + c] = cv;
        sum += cv.x + cv.y + cv.z + cv.w;
        ss  += cv.x*cv.x + cv.y*cv.y + cv.z*cv.z + cv.w*cv.w;
    }
    sum += __shfl_xor_sync(0xffffffffu, sum, 1);
    sum += __shfl_xor_sync(0xffffffffu, sum, 2);
    ss  += __shfl_xor_sync(0xffffffffu, ss, 1);
    ss  += __shfl_xor_sync(0xffffffffu, ss, 2);
    float mu = sum * (1.0f / 256.0f);
    float rstd = rsqrtf(ss * (1.0f / 256.0f) - mu * mu + 1e-5f);
    #pragma unroll
    for (int i = 0; i < 16; i++) {
        int c = qq * 64 + i * 4;
        float4 cv = *(float4*)&Ct[row*260 + c];
        float4 g4 = *(const float4*)&lng[c];
        float4 b4 = *(const float4*)&lnb[c];
        float4 o;
        o.x = (cv.x - mu) * rstd * g4.x + b4.x;
        o.y = (cv.y - mu) * rstd * g4.y + b4.y;
        o.z = (cv.z - mu) * rstd * g4.z + b4.z;
        o.w = (cv.w - mu) * rstd * g4.w + b4.w;
        *(float4*)&C[grow*256 + c] = o;
    }
}

// ================= non-fused GEMM (bias + optional gelu) ======================
// block 64x128, BK=32, 3-stage cp.async, 4 warps (2m x 2n) of 32x64.
template<int ACT>
__global__ __launch_bounds__(128)
void gemm_nf(const float* __restrict__ A, const float* __restrict__ W,
             const float* __restrict__ bias, float* __restrict__ C,
             int N, int Kdim, const int* __restrict__ sep_skip)
{
    const int m0 = blockIdx.y * 64;
    const int n0 = blockIdx.x * 128;
    if (sep_skip) {                               // head GEMM: skip blocks fully below M
        int M_ = *sep_skip;
        if (((m0 + 63) >> 2) < M_) return;
    }

    extern __shared__ float sm[];
    float* Asb = sm;                              // [3][64][36]
    float* Bsb = sm + 3 * 64 * 36;                // [3][128][36]

    const int tid  = threadIdx.x;
    const int lane = tid & 31;
    const int warp = tid >> 5;
    const int grp  = lane >> 2;
    const int qp   = lane & 3;
    const int mw   = (warp >> 1) * 32;
    const int nw   = (warp & 1) * 64;

    const uint32_t asb_u = (uint32_t)__cvta_generic_to_shared(Asb);
    const uint32_t bsb_u = (uint32_t)__cvta_generic_to_shared(Bsb);

    const int nk = Kdim >> 5;

    auto issue_tile = [&](int s, int kt) {
        int k0 = kt << 5;
        #pragma unroll
        for (int i = 0; i < 4; i++) {             // A: 64 rows x 8 float4
            int idx = i*128 + tid;
            int r = idx >> 3, c4 = (idx & 7) * 4;
            cp16(asb_u + (((s*64 + r)*36 + c4) << 2),
                 &A[(size_t)(m0 + r) * Kdim + k0 + c4]);
        }
        #pragma unroll
        for (int i = 0; i < 8; i++) {             // B: 128 rows x 8 float4
            int idx = i*128 + tid;
            int r = idx >> 3, c4 = (idx & 7) * 4;
            cp16(bsb_u + (((s*128 + r)*36 + c4) << 2),
                 &W[(size_t)(n0 + r) * Kdim + k0 + c4]);
        }
        cp_commit();
    };

    float acc[2][8][4];
    #pragma unroll
    for (int mt = 0; mt < 2; mt++)
        #pragma unroll
        for (int nt = 0; nt < 8; nt++)
            #pragma unroll
            for (int e = 0; e < 4; e++) acc[mt][nt][e] = 0.f;

    issue_tile(0, 0);
    issue_tile(1, 1);

    for (int kt = 0; kt < nk; kt++) {
        const int st = kt % 3;
        cp_wait1();
        __syncthreads();
        if (kt + 2 < nk) issue_tile((kt + 2) % 3, kt + 2);
        else             cp_commit();

        const float* As = Asb + st * 64 * 36;
        const float* Bs = Bsb + st * 128 * 36;
        #pragma unroll
        for (int ks = 0; ks < 32; ks += 8) {
            uint32_t af[2][4], bf[8][2];
            #pragma unroll
            for (int mt = 0; mt < 2; mt++) {
                int m = mw + mt * 16 + grp;
                af[mt][0] = f2tf32(As[m*36 + ks + qp]);
                af[mt][1] = f2tf32(As[(m+8)*36 + ks + qp]);
                af[mt][2] = f2tf32(As[m*36 + ks + qp + 4]);
                af[mt][3] = f2tf32(As[(m+8)*36 + ks + qp + 4]);
            }
            #pragma unroll
            for (int nt = 0; nt < 8; nt++) {
                int n = nw + nt * 8 + grp;
                bf[nt][0] = f2tf32(Bs[n*36 + ks + qp]);
                bf[nt][1] = f2tf32(Bs[n*36 + ks + qp + 4]);
            }
            #pragma unroll
            for (int mt = 0; mt < 2; mt++)
                #pragma unroll
                for (int nt = 0; nt < 8; nt++)
                    mma_tf32(acc[mt][nt], af[mt], bf[nt]);
        }
    }

    #pragma unroll
    for (int nt = 0; nt < 8; nt++) {
        int col = n0 + nw + nt * 8 + qp * 2;
        float b0 = bias[col], b1 = bias[col + 1];
        #pragma unroll
        for (int mt = 0; mt < 2; mt++) {
            int row0 = m0 + mw + mt * 16 + grp;
            float v0 = acc[mt][nt][0] + b0;
            float v1 = acc[mt][nt][1] + b1;
            float v2 = acc[mt][nt][2] + b0;
            float v3 = acc[mt][nt][3] + b1;
            if (ACT == 1) { v0 = gelu_exact(v0); v1 = gelu_exact(v1); v2 = gelu_exact(v2); v3 = gelu_exact(v3); }
            *(float2*)&C[(size_t)row0 * N + col]       = make_float2(v0, v1);
            *(float2*)&C[(size_t)(row0 + 8) * N + col] = make_float2(v2, v3);
        }
    }
}

// ---------------- MMA flash attention -----------------------------------------
// keep = (k < M) | (q == k). Reads qkv [ROWS][768] directly, writes merged
// output [ROWS][256]. CTA: 256 queries x one (b,h); 8 warps x 32 queries.
__global__ __launch_bounds__(256)
void attn_mma(const float* __restrict__ qkv, const int* __restrict__ sep,
              float* __restrict__ out)
{
    const int h = blockIdx.y, b = blockIdx.z;
    const int q0 = blockIdx.x * 256;
    const int tid = threadIdx.x;
    const int w = tid >> 5, lane = tid & 31;
    const int grp = lane >> 2, qp = lane & 3;
    const int M_ = *sep;
    const float scale = 0.17677669529663687f;   // 1/sqrt(32)

    __shared__ float Ks [32][36];               // tf32 bits
    __shared__ float Vts[32][36];               // transposed V, tf32 bits
    __shared__ float Ps [8][32][36];            // per-warp P tile; prologue: Q staging

    float* Qst = &Ps[0][0][0];                  // 8*32*36 = 9216 floats = 256*36
    {
        const size_t qbase = ((size_t)q0*4 + b)*768 + (size_t)h*32;
        #pragma unroll
        for (int i = 0; i < 8; i++) {
            int idx = i*256 + tid;
            int r = idx >> 3, c4 = (idx & 7) * 4;
            float4 qv = *(const float4*)&qkv[qbase + (size_t)r*4*768 + c4];
            *(float4*)&Qst[r*36 + c4] = qv;
        }
    }
    __syncthreads();

    uint32_t qf[2][4][4];
    #pragma unroll
    for (int mt = 0; mt < 2; mt++)
        #pragma unroll
        for (int ks = 0; ks < 4; ks++) {
            int r = w*32 + mt*16 + grp;
            qf[mt][ks][0] = f2tf32(Qst[r*36 + ks*8 + qp]);
            qf[mt][ks][1] = f2tf32(Qst[(r+8)*36 + ks*8 + qp]);
            qf[mt][ks][2] = f2tf32(Qst[r*36 + ks*8 + qp + 4]);
            qf[mt][ks][3] = f2tf32(Qst[(r+8)*36 + ks*8 + qp + 4]);
        }

    float acc_o[2][4][4];
    #pragma unroll
    for (int mt = 0; mt < 2; mt++)
        #pragma unroll
        for (int nt = 0; nt < 4; nt++)
            #pragma unroll
            for (int e = 0; e < 4; e++) acc_o[mt][nt][e] = 0.f;
    float m_st[2][2] = {{-1e30f, -1e30f}, {-1e30f, -1e30f}};
    float l_st[2][2] = {{0.f, 0.f}, {0.f, 0.f}};

    const int nch = (M_ + 31) >> 5;
    for (int c = 0; c < nch; c++) {
        const int kbase = c * 32;
        __syncthreads();
        {
            int r = tid >> 3, c4 = (tid & 7) * 4;
            size_t gro = ((size_t)(kbase + r)*4 + b)*768 + (size_t)h*32 + c4;
            float4 kv = *(const float4*)&qkv[gro + 256];
            Ks[r][c4+0] = __uint_as_float(f2tf32(kv.x));
            Ks[r][c4+1] = __uint_as_float(f2tf32(kv.y));
            Ks[r][c4+2] = __uint_as_float(f2tf32(kv.z));
            Ks[r][c4+3] = __uint_as_float(f2tf32(kv.w));
            float4 vv = *(const float4*)&qkv[gro + 512];
            Vts[c4+0][r] = __uint_as_float(f2tf32(vv.x));
            Vts[c4+1][r] = __uint_as_float(f2tf32(vv.y));
            Vts[c4+2][r] = __uint_as_float(f2tf32(vv.z));
            Vts[c4+3][r] = __uint_as_float(f2tf32(vv.w));
        }
        __syncthreads();

        float acc_s[2][4][4];
        #pragma unroll
        for (int mt = 0; mt < 2; mt++)
            #pragma unroll
            for (int nt = 0; nt < 4; nt++)
                #pragma unroll
                for (int e = 0; e < 4; e++) acc_s[mt][nt][e] = 0.f;
        #pragma unroll
        for (int nt = 0; nt < 4; nt++)
            #pragma unroll
            for (int ks = 0; ks < 4; ks++) {
                uint32_t bf[2];
                bf[0] = __float_as_uint(Ks[nt*8 + grp][ks*8 + qp]);
                bf[1] = __float_as_uint(Ks[nt*8 + grp][ks*8 + qp + 4]);
                mma_tf32(acc_s[0][nt], qf[0][ks], bf);
                mma_tf32(acc_s[1][nt], qf[1][ks], bf);
            }

        #pragma unroll
        for (int mt = 0; mt < 2; mt++)
            #pragma unroll
            for (int hf = 0; hf < 2; hf++) {
                float sv[4][2];
                float mx = -1e30f;
                #pragma unroll
                for (int nt = 0; nt < 4; nt++)
                    #pragma unroll
                    for (int j = 0; j < 2; j++) {
                        float s = acc_s[mt][nt][hf*2 + j] * scale;
                        int key = kbase + nt*8 + 2*qp + j;
                        if (key >= M_) s = -1e30f;
                        sv[nt][j] = s;
                        mx = fmaxf(mx, s);
                    }
                mx = fmaxf(mx, __shfl_xor_sync(0xffffffffu, mx, 1));
                mx = fmaxf(mx, __shfl_xor_sync(0xffffffffu, mx, 2));
                float m_old = m_st[mt][hf];
                float m_new = fmaxf(m_old, mx);
                float alpha = __expf(m_old - m_new);
                float rs = 0.f;
                int prow = mt*16 + grp + hf*8;
                #pragma unroll
                for (int nt = 0; nt < 4; nt++) {
                    float p0 = __expf(sv[nt][0] - m_new);
                    float p1 = __expf(sv[nt][1] - m_new);
                    rs += p0 + p1;
                    float2 pp = make_float2(__uint_as_float(f2tf32(p0)),
                                            __uint_as_float(f2tf32(p1)));
                    *(float2*)&Ps[w][prow][nt*8 + 2*qp] = pp;
                }
                rs += __shfl_xor_sync(0xffffffffu, rs, 1);
                rs += __shfl_xor_sync(0xffffffffu, rs, 2);
                l_st[mt][hf] = l_st[mt][hf] * alpha + rs;
                m_st[mt][hf] = m_new;
                #pragma unroll
                for (int ntd = 0; ntd < 4; ntd++) {
                    acc_o[mt][ntd][hf*2 + 0] *= alpha;
                    acc_o[mt][ntd][hf*2 + 1] *= alpha;
                }
            }
        __syncwarp();

        #pragma unroll
        for (int ks = 0; ks < 4; ks++) {
            uint32_t af[2][4];
            #pragma unroll
            for (int mt = 0; mt < 2; mt++) {
                int r = mt*16 + grp;
                af[mt][0] = __float_as_uint(Ps[w][r][ks*8 + qp]);
                af[mt][1] = __float_as_uint(Ps[w][r + 8][ks*8 + qp]);
                af[mt][2] = __float_as_uint(Ps[w][r][ks*8 + qp + 4]);
                af[mt][3] = __float_as_uint(Ps[w][r + 8][ks*8 + qp + 4]);
            }
            #pragma unroll
            for (int ntd = 0; ntd < 4; ntd++) {
                uint32_t bf[2];
                bf[0] = __float_as_uint(Vts[ntd*8 + grp][ks*8 + qp]);
                bf[1] = __float_as_uint(Vts[ntd*8 + grp][ks*8 + qp + 4]);
                mma_tf32(acc_o[0][ntd], af[0], bf);
                mma_tf32(acc_o[1][ntd], af[1], bf);
            }
        }
    }

    // ---- diagonal key for q >= M ----
    #pragma unroll
    for (int mt = 0; mt < 2; mt++)
        #pragma unroll
        for (int hf = 0; hf < 2; hf++) {
            int q_g = q0 + w*32 + mt*16 + grp + hf*8;
            bool active = (q_g >= M_);
            float part = 0.f;
            size_t rbase = ((size_t)q_g*4 + b)*768 + (size_t)h*32;
            if (active) {
                #pragma unroll
                for (int ks = 0; ks < 4; ks++) {
                    float k0 = qkv[rbase + 256 + ks*8 + qp];
                    float k1 = qkv[rbase + 256 + ks*8 + qp + 4];
                    float qa = __uint_as_float(qf[mt][ks][hf ? 1 : 0]);
                    float qb = __uint_as_float(qf[mt][ks][hf ? 3 : 2]);
                    part += qa*k0 + qb*k1;
                }
            }
            part += __shfl_xor_sync(0xffffffffu, part, 1);
            part += __shfl_xor_sync(0xffffffffu, part, 2);
            if (active) {
                float s_d = part * scale;
                float m_old = m_st[mt][hf];
                float m_new = fmaxf(m_old, s_d);
                float alpha = __expf(m_old - m_new);
                float pd = __expf(s_d - m_new);
                l_st[mt][hf] = l_st[mt][hf] * alpha + pd;
                m_st[mt][hf] = m_new;
                #pragma unroll
                for (int ntd = 0; ntd < 4; ntd++) {
                    float v0 = qkv[rbase + 512 + ntd*8 + 2*qp];
                    float v1 = qkv[rbase + 512 + ntd*8 + 2*qp + 1];
                    acc_o[mt][ntd][hf*2 + 0] = acc_o[mt][ntd][hf*2 + 0]*alpha + pd*v0;
                    acc_o[mt][ntd][hf*2 + 1] = acc_o[mt][ntd][hf*2 + 1]*alpha + pd*v1;
                }
            }
        }

    // ---- finalize ----
    #pragma unroll
    for (int mt = 0; mt < 2; mt++)
        #pragma unroll
        for (int hf = 0; hf < 2; hf++) {
            int q_g = q0 + w*32 + mt*16 + grp + hf*8;
            size_t orow = ((size_t)q_g*4 + b)*256 + (size_t)h*32;
            float inv = 1.f / l_st[mt][hf];
            #pragma unroll
            for (int ntd = 0; ntd < 4; ntd++) {
                float2 o2 = make_float2(acc_o[mt][ntd][hf*2 + 0] * inv,
                                        acc_o[mt][ntd][hf*2 + 1] * inv);
                *(float2*)&out[orow + ntd*8 + 2*qp] = o2;
            }
        }
}

// ---------------- final head: out[(s-M)*B+b] = hid . w2 + b2 -----------------
__global__ void head2_kernel(const float* __restrict__ hid, const float* __restrict__ w2,
                             const float* __restrict__ b2, const int* __restrict__ sep,
                             float* __restrict__ out)
{
    int row = blockIdx.x;
    int M_ = *sep;
    int s = row >> 2, b = row & 3;
    if (s < M_) return;
    float sum = 0.f;
    for (int t = threadIdx.x; t < DFF; t += 128)
        sum += hid[(size_t)row*DFF + t] * w2[t];
    for (int off = 16; off > 0; off >>= 1)
        sum += __shfl_down_sync(0xffffffffu, sum, off);
    __shared__ float ws[4];
    if ((threadIdx.x & 31) == 0) ws[threadIdx.x >> 5] = sum;
    __syncthreads();
    if (threadIdx.x == 0)
        out[(s - M_)*BT + b] = ws[0] + ws[1] + ws[2] + ws[3] + b2[0];
}

// =============================================================================
extern "C" void kernel_launch(void* const* d_in, const int* in_sizes, int n_in,
                              void* d_out, int out_size)
{
    (void)in_sizes; (void)n_in; (void)out_size;
    const float* x        = (const float*)d_in[0];
    const float* y        = (const float*)d_in[1];
    const int*   sep      = (const int*  )d_in[2];
    const float* xenc_w   = (const float*)d_in[3];
    const float* xenc_b   = (const float*)d_in[4];
    const float* yenc_w   = (const float*)d_in[5];
    const float* yenc_b   = (const float*)d_in[6];
    const float* in_proj_w= (const float*)d_in[7];
    const float* in_proj_b= (const float*)d_in[8];
    const float* out_proj_w=(const float*)d_in[9];
    const float* out_proj_b=(const float*)d_in[10];
    const float* ln1_g    = (const float*)d_in[11];
    const float* ln1_b    = (const float*)d_in[12];
    const float* lin1_w   = (const float*)d_in[13];
    const float* lin1_b   = (const float*)d_in[14];
    const float* lin2_w   = (const float*)d_in[15];
    const float* lin2_b   = (const float*)d_in[16];
    const float* ln2_g    = (const float*)d_in[17];
    const float* ln2_b    = (const float*)d_in[18];
    const float* head_w1  = (const float*)d_in[19];
    const float* head_b1  = (const float*)d_in[20];
    const float* head_w2  = (const float*)d_in[21];
    const float* head_b2  = (const float*)d_in[22];
    float* out = (float*)d_out;

    float *h, *qkv, *tmp, *ff;
    cudaGetSymbolAddress((void**)&h,    g_h);
    cudaGetSymbolAddress((void**)&qkv,  g_qkv);
    cudaGetSymbolAddress((void**)&tmp,  g_tmp);
    cudaGetSymbolAddress((void**)&ff,   g_ff);

    const int fuse_smem = FUSE_SMEM_FLOATS * 4;   // 138240 B
    const int nf_smem   = NF_SMEM_FLOATS * 4;     // 82944 B
    cudaFuncSetAttribute(gemm_fuse,  cudaFuncAttributeMaxDynamicSharedMemorySize, fuse_smem);
    cudaFuncSetAttribute(gemm_nf<0>, cudaFuncAttributeMaxDynamicSharedMemorySize, nf_smem);
    cudaFuncSetAttribute(gemm_nf<1>, cudaFuncAttributeMaxDynamicSharedMemorySize, nf_smem);

    embed_kernel<<<ROWS, DM>>>(x, y, sep, xenc_w, xenc_b, yenc_w, yenc_b, h);

    for (int l = 0; l < NL; l++) {
        // QKV projection: (8192 x 256) x (768 x 256)^T
        gemm_nf<0><<<dim3(6, ROWS/64), 128, nf_smem>>>(
            h, in_proj_w + (size_t)l*3*DM*DM, in_proj_b + (size_t)l*3*DM, qkv, 3*DM, DM, nullptr);
        attn_mma<<<dim3(SEQ/256, NHD, BT), 256>>>(qkv, sep, tmp);
        // out projection fused with residual+LN -> writes h
        gemm_fuse<<<dim3(1, ROWS/64), 256, fuse_smem>>>(
            tmp, out_proj_w + (size_t)l*DM*DM, out_proj_b + (size_t)l*DM, h,
            h, ln1_g + (size_t)l*DM, ln1_b + (size_t)l*DM, DM);
        // FF up with gelu
        gemm_nf<1><<<dim3(4, ROWS/64), 128, nf_smem>>>(
            h, lin1_w + (size_t)l*DFF*DM, lin1_b + (size_t)l*DFF, ff, DFF, DM, nullptr);
        // FF down fused with residual+LN -> writes h
        gemm_fuse<<<dim3(1, ROWS/64), 256, fuse_smem>>>(
            ff, lin2_w + (size_t)l*DM*DFF, lin2_b + (size_t)l*DM, h,
            h, ln2_g + (size_t)l*DM, ln2_b + (size_t)l*DM, DFF);
    }

    gemm_nf<1><<<dim3(4, ROWS/64), 128, nf_smem>>>(
        h, head_w1, head_b1, ff, DFF, DM, sep);
    head2_kernel<<<ROWS, 128>>>(ff, head_w2, head_b2, sep, out);
}